// round 6
// baseline (speedup 1.0000x reference)
#include <cuda_runtime.h>
#include <cuda_fp16.h>
#include <cstdint>

// ============================================================
// LIIF_3d via HMMA (mma.sync m16n8k16 fp16, f32 accum, hi/lo 3-split).
// M=64 queries/CTA, 256 threads, K-chunk=32 -> smem 109.6KB -> occupancy 2
// (cross-CTA overlap hides staging + barriers). L4 done in fp32 FFMA.
// ============================================================

#define HH   256
#define WWI  256
#define QN   65536
#define CIN  64
#define W0F  30.0f
#define MQ   64
#define SA   264           // A row stride (halfs): 256 + 8 pad, conflict-free ldmatrix
#define SB   40            // B row stride (halfs): 32 + 8 pad

#define SM_COORD 0                          // qy[64] qx[64] tv[64]
#define SM_AHI   1024
#define SM_ALO   (SM_AHI + MQ * SA * 2)     // 34816
#define SM_BHI   (SM_ALO + MQ * SA * 2)     // 68608
#define SM_BLO   (SM_BHI + 256 * SB * 2)    // 89088
#define SM_TOTAL (SM_BLO + 256 * SB * 2)    // 109568

// transposed split weights [n][kp] per segment: L0 256x640 (k>=577 zero,
// k==576 = t column); L1-3 256x256. (L4 handled in fp32 directly.)
#define WT_ELEMS 360448
__device__ __half g_wt_hi[WT_ELEMS];
__device__ __half g_wt_lo[WT_ELEMS];
__device__ float  g_pat[2 * QN * 27];

static __device__ __forceinline__ uint32_t smem_u32(const void* p) {
    uint32_t a;
    asm("{ .reg .u64 t; cvta.to.shared.u64 t, %1; cvt.u32.u64 %0, t; }" : "=r"(a) : "l"(p));
    return a;
}

#define LDSM4(r, addr)                                                              \
    asm volatile("ldmatrix.sync.aligned.m8n8.x4.shared.b16 {%0,%1,%2,%3}, [%4];"    \
                 : "=r"((r)[0]), "=r"((r)[1]), "=r"((r)[2]), "=r"((r)[3])           \
                 : "r"(addr) : "memory")

static __device__ __forceinline__ void mma16816(float* c, const uint32_t* a, const uint32_t* b) {
    asm volatile(
        "mma.sync.aligned.m16n8k16.row.col.f32.f16.f16.f32 "
        "{%0,%1,%2,%3}, {%4,%5,%6,%7}, {%8,%9}, {%0,%1,%2,%3};"
        : "+f"(c[0]), "+f"(c[1]), "+f"(c[2]), "+f"(c[3])
        : "r"(a[0]), "r"(a[1]), "r"(a[2]), "r"(a[3]), "r"(b[0]), "r"(b[1]));
}

// ---------------- prep: transpose + hi/lo split ----------------
__global__ void prep_kernel(const float* __restrict__ w0, const float* __restrict__ w1,
                            const float* __restrict__ w2, const float* __restrict__ w3) {
    int i = blockIdx.x * 256 + threadIdx.x;
    if (i >= WT_ELEMS) return;
    float v;
    if (i < 163840) {                 // L0 [256][640]
        int n = i / 640, k = i - n * 640;
        v = (k < 577) ? w0[k * 256 + n] : 0.0f;
    } else if (i < 229376) {
        int j = i - 163840; int n = j >> 8, k = j & 255; v = w1[k * 256 + n];
    } else if (i < 294912) {
        int j = i - 229376; int n = j >> 8, k = j & 255; v = w2[k * 256 + n];
    } else {
        int j = i - 294912; int n = j >> 8, k = j & 255; v = w3[k * 256 + n];
    }
    __half h = __float2half_rn(v);
    g_wt_hi[i] = h;
    g_wt_lo[i] = __float2half_rn(v - __half2float(h));
}

// ---------------- fused MLP ----------------
__global__ __launch_bounds__(256, 2)
void mlp_hmma(const float* __restrict__ feat, const float* __restrict__ coord,
              const float* __restrict__ b0, const float* __restrict__ b1,
              const float* __restrict__ b2, const float* __restrict__ b3,
              const float* __restrict__ w4, const float* __restrict__ b4) {
    extern __shared__ char smem[];
    const uint32_t sb = smem_u32(smem);
    int*   qy = (int*)(smem + SM_COORD);
    int*   qx = qy + MQ;
    float* tv = (float*)(qx + MQ);

    const int tid  = threadIdx.x;
    const int lane = tid & 31;
    const int w    = tid >> 5;
    const int wm   = w >> 2;           // 0..1  (M groups of 32 rows)
    const int wn   = w & 3;            // 0..3  (N groups of 64 cols)
    const int qbase = blockIdx.x * MQ;
    const int bimg  = qbase >> 16;

    if (tid < MQ) {
        int qg = qbase + tid;
        int q  = qg & (QN - 1);
        const float* cp = coord + (bimg * QN + q) * 3;
        float cy = cp[0], cx = cp[1];
        const float e = 1e-6f;
        cy = fminf(fmaxf(cy, -1.0f + e), 1.0f - e);
        cx = fminf(fmaxf(cx, -1.0f + e), 1.0f - e);
        int iy = (int)rintf((cy + 1.0f) * (HH * 0.5f) - 0.5f);
        int ix = (int)rintf((cx + 1.0f) * (WWI * 0.5f) - 0.5f);
        qy[tid] = min(max(iy, 0), HH - 1);
        qx[tid] = min(max(ix, 0), WWI - 1);
        tv[tid] = cp[2];
    }
    __syncthreads();

    const float* Bias[4] = {b0, b1, b2, b3};
    const int seg[4] = {0, 163840, 229376, 294912};
    const int kps[4] = {640, 256, 256, 256};

    const int rowbase = wm * 32;
    const uint32_t a_off = (uint32_t)(((rowbase + (lane & 15)) * SA + ((lane >> 4) << 3)) * 2);
    const uint32_t aHi = sb + SM_AHI + a_off;
    const uint32_t aLo = sb + SM_ALO + a_off;
    const uint32_t b_off = (uint32_t)(((wn * 64 + ((lane >> 4) << 3) + (lane & 7)) * SB +
                                      ((lane >> 3) & 1) * 8) * 2);
    const uint32_t bHi = sb + SM_BHI + b_off;
    const uint32_t bLo = sb + SM_BLO + b_off;

    float acc[2][8][4];

    for (int l = 0; l < 4; l++) {
        #pragma unroll
        for (int mt = 0; mt < 2; mt++)
            #pragma unroll
            for (int nt = 0; nt < 8; nt++)
                #pragma unroll
                for (int i = 0; i < 4; i++) acc[mt][nt][i] = 0.0f;

        const int kp = kps[l];
        const int nstages = (l == 0) ? 3 : 1;

        for (int s = 0; s < nstages; s++) {
            const int klen = (l == 0) ? ((s < 2) ? 256 : 128) : 256;
            __syncthreads();                        // A region free
            if (l == 0) {
                for (int idx = tid; idx < MQ * klen; idx += 256) {
                    int q = idx & (MQ - 1);
                    int j = idx >> 6;
                    int k = s * 256 + j;
                    float v = 0.0f;
                    if (k < 576) {
                        int ci = k / 9, r9 = k - ci * 9;
                        int di = r9 / 3, dj = r9 - di * 3;
                        int yy = qy[q] + di - 1, xx = qx[q] + dj - 1;
                        if (yy >= 0 && yy < HH && xx >= 0 && xx < WWI)
                            v = __ldg(feat + ((bimg * CIN + ci) * HH + yy) * WWI + xx);
                    } else if (k == 576) {
                        v = tv[q];
                    }
                    __half h  = __float2half_rn(v);
                    __half lo = __float2half_rn(v - __half2float(h));
                    uint32_t off = (uint32_t)((q * SA + j) * 2);
                    *(__half*)(smem + SM_AHI + off) = h;
                    *(__half*)(smem + SM_ALO + off) = lo;
                }
            }
            const int nch = klen >> 5;               // K-chunks of 32
            for (int c = 0; c < nch; c++) {
                const int kg = s * 256 + c * 32;
                __syncthreads();                     // B buffer free (and gather visible)
                for (int idx = tid; idx < 256 * 4; idx += 256) {
                    int n = idx >> 2, u = idx & 3;
                    uint32_t soff = (uint32_t)((n * SB + u * 8) * 2);
                    const __half* ph = g_wt_hi + seg[l] + n * kp + kg + u * 8;
                    const __half* pl = g_wt_lo + seg[l] + n * kp + kg + u * 8;
                    *(uint4*)(smem + SM_BHI + soff) = *(const uint4*)ph;
                    *(uint4*)(smem + SM_BLO + soff) = *(const uint4*)pl;
                }
                __syncthreads();
                #pragma unroll
                for (int ks = 0; ks < 2; ks++) {
                    const uint32_t ca2 = (uint32_t)((c * 32 + ks * 16) * 2);
                    uint32_t Ah[8], Al[8];
                    LDSM4(Ah,     aHi + ca2);
                    LDSM4(Ah + 4, aHi + ca2 + 16 * SA * 2);
                    LDSM4(Al,     aLo + ca2);
                    LDSM4(Al + 4, aLo + ca2 + 16 * SA * 2);
                    {
                        uint32_t Bh[16];
                        #pragma unroll
                        for (int p = 0; p < 4; p++)
                            LDSM4(Bh + 4 * p, bHi + (uint32_t)(p * 16 * SB * 2 + ks * 32));
                        #pragma unroll
                        for (int mt = 0; mt < 2; mt++)
                            #pragma unroll
                            for (int nt = 0; nt < 8; nt++)
                                mma16816(acc[mt][nt], Ah + 4 * mt, Bh + 2 * nt);
                        #pragma unroll
                        for (int mt = 0; mt < 2; mt++)
                            #pragma unroll
                            for (int nt = 0; nt < 8; nt++)
                                mma16816(acc[mt][nt], Al + 4 * mt, Bh + 2 * nt);
                    }
                    {
                        uint32_t Bl[16];
                        #pragma unroll
                        for (int p = 0; p < 4; p++)
                            LDSM4(Bl + 4 * p, bLo + (uint32_t)(p * 16 * SB * 2 + ks * 32));
                        #pragma unroll
                        for (int mt = 0; mt < 2; mt++)
                            #pragma unroll
                            for (int nt = 0; nt < 8; nt++)
                                mma16816(acc[mt][nt], Ah + 4 * mt, Bl + 2 * nt);
                    }
                }
            }
        }

        __syncthreads();   // all warps done reading A before epilogue overwrites it
        {
            const float* bp = Bias[l];
            const int trow  = rowbase + (lane >> 2);
            const int tcol0 = wn * 64 + 2 * (lane & 3);
            #pragma unroll
            for (int mt = 0; mt < 2; mt++) {
                #pragma unroll
                for (int nt = 0; nt < 8; nt++) {
                    int col = tcol0 + nt * 8;
                    float2 bb = *(const float2*)(bp + col);
                    int r0 = trow + mt * 16;
                    int r1 = r0 + 8;
                    float v00 = __sinf(W0F * (acc[mt][nt][0] + bb.x));
                    float v01 = __sinf(W0F * (acc[mt][nt][1] + bb.y));
                    float v10 = __sinf(W0F * (acc[mt][nt][2] + bb.x));
                    float v11 = __sinf(W0F * (acc[mt][nt][3] + bb.y));
                    __half h00 = __float2half_rn(v00), h01 = __float2half_rn(v01);
                    __half h10 = __float2half_rn(v10), h11 = __float2half_rn(v11);
                    __half l00 = __float2half_rn(v00 - __half2float(h00));
                    __half l01 = __float2half_rn(v01 - __half2float(h01));
                    __half l10 = __float2half_rn(v10 - __half2float(h10));
                    __half l11 = __float2half_rn(v11 - __half2float(h11));
                    uint32_t o0 = (uint32_t)((r0 * SA + col) * 2);
                    uint32_t o1 = (uint32_t)((r1 * SA + col) * 2);
                    *(__half2*)(smem + SM_AHI + o0) = __halves2half2(h00, h01);
                    *(__half2*)(smem + SM_ALO + o0) = __halves2half2(l00, l01);
                    *(__half2*)(smem + SM_AHI + o1) = __halves2half2(h10, h11);
                    *(__half2*)(smem + SM_ALO + o1) = __halves2half2(l10, l11);
                }
            }
        }
    }

    // ---------------- L4: 256 -> 27 in fp32 FFMA ----------------
    {
        float* ws = (float*)(smem + SM_BHI);          // 256*27 floats = 27648B
        for (int i = tid; i < 256 * 27; i += 256) ws[i] = __ldg(w4 + i);
        __syncthreads();                              // ws + A(epilogue l3) visible

        const int q  = tid >> 2;                      // 0..63
        const int cj = tid & 3;
        const __half* Ahp = (const __half*)(smem + SM_AHI) + q * SA;
        const __half* Alp = (const __half*)(smem + SM_ALO) + q * SA;
        float a4[7];
        #pragma unroll
        for (int j = 0; j < 7; j++) a4[j] = 0.0f;
        #pragma unroll 4
        for (int k = 0; k < 256; k++) {
            float a = __half2float(Ahp[k]) + __half2float(Alp[k]);
            #pragma unroll
            for (int j = 0; j < 7; j++) {
                int c = cj + 4 * j;
                if (c < 27) a4[j] = fmaf(a, ws[k * 27 + c], a4[j]);
            }
        }
        const int qg = qbase + q;
        #pragma unroll
        for (int j = 0; j < 7; j++) {
            int c = cj + 4 * j;
            if (c < 27) g_pat[qg * 27 + c] = a4[j] + __ldg(b4 + c);
        }
    }
}

// ---------------- fold3 ----------------
__global__ void fold_kernel(float* __restrict__ out) {
    int idx = blockIdx.x * blockDim.x + threadIdx.x;
    if (idx >= 2 * QN) return;
    int b = idx >> 16;
    int p = idx & (QN - 1);
    int y = p >> 8, x = p & 255;
    float s0 = 0.f, s1 = 0.f, s2 = 0.f;
    #pragma unroll
    for (int i = 0; i < 3; i++) {
        int yy = y + 1 - i;
        if (yy < 0 || yy >= HH) continue;
        #pragma unroll
        for (int j = 0; j < 3; j++) {
            int xx = x + 1 - j;
            if (xx < 0 || xx >= WWI) continue;
            const float* pp = g_pat + (b * QN + yy * WWI + xx) * 27 + i * 3 + j;
            s0 += pp[0];
            s1 += pp[9];
            s2 += pp[18];
        }
    }
    out[(b * 3 + 0) * QN + p] = s0;
    out[(b * 3 + 1) * QN + p] = s1;
    out[(b * 3 + 2) * QN + p] = s2;
}

extern "C" void kernel_launch(void* const* d_in, const int* in_sizes, int n_in,
                              void* d_out, int out_size) {
    const float* feat  = (const float*)d_in[0];
    const float* coord = (const float*)d_in[1];
    const float* w0 = (const float*)d_in[2];
    const float* b0 = (const float*)d_in[3];
    const float* w1 = (const float*)d_in[4];
    const float* b1 = (const float*)d_in[5];
    const float* w2 = (const float*)d_in[6];
    const float* b2 = (const float*)d_in[7];
    const float* w3 = (const float*)d_in[8];
    const float* b3 = (const float*)d_in[9];
    const float* w4 = (const float*)d_in[10];
    const float* b4 = (const float*)d_in[11];
    float* out = (float*)d_out;

    prep_kernel<<<(WT_ELEMS + 255) / 256, 256>>>(w0, w1, w2, w3);

    cudaFuncSetAttribute(mlp_hmma, cudaFuncAttributeMaxDynamicSharedMemorySize, SM_TOTAL);
    mlp_hmma<<<(2 * QN) / MQ, 256, SM_TOTAL>>>(feat, coord, b0, b1, b2, b3, w4, b4);

    fold_kernel<<<(2 * QN + 255) / 256, 256>>>(out);
}

// round 7
// speedup vs baseline: 1.1048x; 1.1048x over previous
#include <cuda_runtime.h>
#include <cuda_fp16.h>
#include <cstdint>

// ============================================================
// LIIF_3d via HMMA hi/lo 3-split:
//   hi*hi  -> mma.sync m16n8k16 f32 accum
//   al*bh + ah*bl -> shared f16 accum (flushed to f32 each 64-K chunk)
// MQ=128 queries/CTA, 512 threads, warp tile 32x64.
// L0 trimmed to K=576 (t handled as exact rank-1 in epilogue).
// L4 (256->27) in fp32 FFMA. fold3 separate kernel.
// ============================================================

#define HH   256
#define WWI  256
#define QN   65536
#define CIN  64
#define W0F  30.0f
#define MQ   128
#define SA   264           // A row stride (halfs): 256 + 8 pad
#define SB   72            // B row stride (halfs): 64 + 8 pad

#define SM_COORD 0                          // qy[128] qx[128] tv[128]
#define SM_AHI   2048
#define SM_ALO   (SM_AHI + MQ * SA * 2)     // 69632
#define SM_BHI   (SM_ALO + MQ * SA * 2)     // 137216
#define SM_BLO   (SM_BHI + 256 * SB * 2)    // 174080
#define SM_TOTAL (SM_BLO + 256 * SB * 2)    // 210944

// transposed split weights [n][kp]: L0 256x640 (cols>=577 zero), L1-3 256x256
#define WT_ELEMS 360448
__device__ __half g_wt_hi[WT_ELEMS];
__device__ __half g_wt_lo[WT_ELEMS];
__device__ float  g_pat[2 * QN * 27];

static __device__ __forceinline__ uint32_t smem_u32(const void* p) {
    uint32_t a;
    asm("{ .reg .u64 t; cvta.to.shared.u64 t, %1; cvt.u32.u64 %0, t; }" : "=r"(a) : "l"(p));
    return a;
}

#define LDSM4(r, addr)                                                              \
    asm volatile("ldmatrix.sync.aligned.m8n8.x4.shared.b16 {%0,%1,%2,%3}, [%4];"    \
                 : "=r"((r)[0]), "=r"((r)[1]), "=r"((r)[2]), "=r"((r)[3])           \
                 : "r"(addr) : "memory")

static __device__ __forceinline__ void mma_f32(float* c, const uint32_t* a, const uint32_t* b) {
    asm volatile(
        "mma.sync.aligned.m16n8k16.row.col.f32.f16.f16.f32 "
        "{%0,%1,%2,%3}, {%4,%5,%6,%7}, {%8,%9}, {%0,%1,%2,%3};"
        : "+f"(c[0]), "+f"(c[1]), "+f"(c[2]), "+f"(c[3])
        : "r"(a[0]), "r"(a[1]), "r"(a[2]), "r"(a[3]), "r"(b[0]), "r"(b[1]));
}

static __device__ __forceinline__ void mma_f16(uint32_t* c, const uint32_t* a, const uint32_t* b) {
    asm volatile(
        "mma.sync.aligned.m16n8k16.row.col.f16.f16.f16.f16 "
        "{%0,%1}, {%2,%3,%4,%5}, {%6,%7}, {%0,%1};"
        : "+r"(c[0]), "+r"(c[1])
        : "r"(a[0]), "r"(a[1]), "r"(a[2]), "r"(a[3]), "r"(b[0]), "r"(b[1]));
}

// ---------------- prep: transpose + hi/lo split ----------------
__global__ void prep_kernel(const float* __restrict__ w0, const float* __restrict__ w1,
                            const float* __restrict__ w2, const float* __restrict__ w3) {
    int i = blockIdx.x * 256 + threadIdx.x;
    if (i >= WT_ELEMS) return;
    float v;
    if (i < 163840) {                 // L0 [256][640]
        int n = i / 640, k = i - n * 640;
        v = (k < 577) ? w0[k * 256 + n] : 0.0f;
    } else if (i < 229376) {
        int j = i - 163840; int n = j >> 8, k = j & 255; v = w1[k * 256 + n];
    } else if (i < 294912) {
        int j = i - 229376; int n = j >> 8, k = j & 255; v = w2[k * 256 + n];
    } else {
        int j = i - 294912; int n = j >> 8, k = j & 255; v = w3[k * 256 + n];
    }
    __half h = __float2half_rn(v);
    g_wt_hi[i] = h;
    g_wt_lo[i] = __float2half_rn(v - __half2float(h));
}

// ---------------- fused MLP ----------------
__global__ __launch_bounds__(512, 1)
void mlp_hmma(const float* __restrict__ feat, const float* __restrict__ coord,
              const float* __restrict__ w0_raw,
              const float* __restrict__ b0, const float* __restrict__ b1,
              const float* __restrict__ b2, const float* __restrict__ b3,
              const float* __restrict__ w4, const float* __restrict__ b4) {
    extern __shared__ char smem[];
    const uint32_t sb = smem_u32(smem);
    int*   qy = (int*)(smem + SM_COORD);
    int*   qx = qy + MQ;
    float* tv = (float*)(qx + MQ);

    const int tid  = threadIdx.x;
    const int lane = tid & 31;
    const int w    = tid >> 5;
    const int wm   = w >> 2;           // 0..3  (M groups of 32 rows)
    const int wn   = w & 3;            // 0..3  (N groups of 64 cols)
    const int qbase = blockIdx.x * MQ;
    const int bimg  = qbase >> 16;

    if (tid < MQ) {
        int qg = qbase + tid;
        int q  = qg & (QN - 1);
        const float* cp = coord + (bimg * QN + q) * 3;
        float cy = cp[0], cx = cp[1];
        const float e = 1e-6f;
        cy = fminf(fmaxf(cy, -1.0f + e), 1.0f - e);
        cx = fminf(fmaxf(cx, -1.0f + e), 1.0f - e);
        int iy = (int)rintf((cy + 1.0f) * (HH * 0.5f) - 0.5f);
        int ix = (int)rintf((cx + 1.0f) * (WWI * 0.5f) - 0.5f);
        qy[tid] = min(max(iy, 0), HH - 1);
        qx[tid] = min(max(ix, 0), WWI - 1);
        tv[tid] = cp[2];
    }
    __syncthreads();

    const float* Bias[4] = {b0, b1, b2, b3};
    const int seg[4] = {0, 163840, 229376, 294912};
    const int kps[4] = {640, 256, 256, 256};

    const int rowbase = wm * 32;
    const uint32_t a_off = (uint32_t)(((rowbase + (lane & 15)) * SA + ((lane >> 4) << 3)) * 2);
    const uint32_t aHi = sb + SM_AHI + a_off;
    const uint32_t aLo = sb + SM_ALO + a_off;
    const uint32_t b_off = (uint32_t)(((wn * 64 + ((lane >> 4) << 3) + (lane & 7)) * SB +
                                      ((lane >> 3) & 1) * 8) * 2);
    const uint32_t bHi = sb + SM_BHI + b_off;
    const uint32_t bLo = sb + SM_BLO + b_off;

    float acc[2][8][4];

    for (int l = 0; l < 4; l++) {
        #pragma unroll
        for (int mt = 0; mt < 2; mt++)
            #pragma unroll
            for (int nt = 0; nt < 8; nt++)
                #pragma unroll
                for (int i = 0; i < 4; i++) acc[mt][nt][i] = 0.0f;

        const int kp = kps[l];
        const int nstages = (l == 0) ? 3 : 1;

        for (int s = 0; s < nstages; s++) {
            // L0 K=576 exactly: stages 256,256,64
            const int klen = (l == 0) ? ((s < 2) ? 256 : 64) : 256;
            __syncthreads();                        // A region free
            if (l == 0) {
                for (int idx = tid; idx < MQ * klen; idx += 512) {
                    int q = idx & (MQ - 1);
                    int j = idx >> 7;
                    int k = s * 256 + j;            // always < 576 here
                    int ci = k / 9, r9 = k - ci * 9;
                    int di = r9 / 3, dj = r9 - di * 3;
                    int yy = qy[q] + di - 1, xx = qx[q] + dj - 1;
                    float v = (yy >= 0 && yy < HH && xx >= 0 && xx < WWI)
                        ? __ldg(feat + ((bimg * CIN + ci) * HH + yy) * WWI + xx) : 0.0f;
                    __half h  = __float2half_rn(v);
                    __half lo = __float2half_rn(v - __half2float(h));
                    uint32_t off = (uint32_t)((q * SA + j) * 2);
                    *(__half*)(smem + SM_AHI + off) = h;
                    *(__half*)(smem + SM_ALO + off) = lo;
                }
            }
            const int nch = klen >> 6;
            for (int c = 0; c < nch; c++) {
                const int kg = s * 256 + c * 64;
                __syncthreads();                    // B buffer free (and gather visible)
                for (int idx = tid; idx < 256 * 8; idx += 512) {
                    int n = idx >> 3, u = idx & 7;
                    uint32_t soff = (uint32_t)((n * SB + u * 8) * 2);
                    const __half* ph = g_wt_hi + seg[l] + n * kp + kg + u * 8;
                    const __half* pl = g_wt_lo + seg[l] + n * kp + kg + u * 8;
                    *(uint4*)(smem + SM_BHI + soff) = *(const uint4*)ph;
                    *(uint4*)(smem + SM_BLO + soff) = *(const uint4*)pl;
                }
                __syncthreads();

                // f16 correction accumulators for this 64-K chunk
                uint32_t corr[2][8][2];
                #pragma unroll
                for (int mt = 0; mt < 2; mt++)
                    #pragma unroll
                    for (int nt = 0; nt < 8; nt++) {
                        corr[mt][nt][0] = 0u; corr[mt][nt][1] = 0u;
                    }

                #pragma unroll
                for (int ks = 0; ks < 4; ks++) {
                    const uint32_t ca2 = (uint32_t)((c * 64 + ks * 16) * 2);
                    uint32_t Ah[8], Al[8];
                    LDSM4(Ah,     aHi + ca2);
                    LDSM4(Ah + 4, aHi + ca2 + 16 * SA * 2);
                    LDSM4(Al,     aLo + ca2);
                    LDSM4(Al + 4, aLo + ca2 + 16 * SA * 2);
                    {
                        uint32_t Bh[16];
                        #pragma unroll
                        for (int p = 0; p < 4; p++)
                            LDSM4(Bh + 4 * p, bHi + (uint32_t)(p * 16 * SB * 2 + ks * 32));
                        #pragma unroll
                        for (int mt = 0; mt < 2; mt++)
                            #pragma unroll
                            for (int nt = 0; nt < 8; nt++)
                                mma_f32(acc[mt][nt], Ah + 4 * mt, Bh + 2 * nt);
                        #pragma unroll
                        for (int mt = 0; mt < 2; mt++)
                            #pragma unroll
                            for (int nt = 0; nt < 8; nt++)
                                mma_f16(corr[mt][nt], Al + 4 * mt, Bh + 2 * nt);
                    }
                    {
                        uint32_t Bl[16];
                        #pragma unroll
                        for (int p = 0; p < 4; p++)
                            LDSM4(Bl + 4 * p, bLo + (uint32_t)(p * 16 * SB * 2 + ks * 32));
                        #pragma unroll
                        for (int mt = 0; mt < 2; mt++)
                            #pragma unroll
                            for (int nt = 0; nt < 8; nt++)
                                mma_f16(corr[mt][nt], Ah + 4 * mt, Bl + 2 * nt);
                    }
                }
                // flush f16 corrections into f32 accumulators
                #pragma unroll
                for (int mt = 0; mt < 2; mt++)
                    #pragma unroll
                    for (int nt = 0; nt < 8; nt++) {
                        float2 f0 = __half22float2(*(const __half2*)&corr[mt][nt][0]);
                        float2 f1 = __half22float2(*(const __half2*)&corr[mt][nt][1]);
                        acc[mt][nt][0] += f0.x; acc[mt][nt][1] += f0.y;
                        acc[mt][nt][2] += f1.x; acc[mt][nt][3] += f1.y;
                    }
            }
        }

        __syncthreads();   // all warps done reading A before epilogue overwrites it
        {
            const float* bp = Bias[l];
            const int trow  = rowbase + (lane >> 2);
            const int tcol0 = wn * 64 + 2 * (lane & 3);
            #pragma unroll
            for (int mt = 0; mt < 2; mt++) {
                const int r0 = trow + mt * 16;
                const int r1 = r0 + 8;
                const float tv0 = tv[r0], tv1 = tv[r1];
                #pragma unroll
                for (int nt = 0; nt < 8; nt++) {
                    int col = tcol0 + nt * 8;
                    float2 bb = *(const float2*)(bp + col);
                    float a0 = acc[mt][nt][0], a1 = acc[mt][nt][1];
                    float a2 = acc[mt][nt][2], a3 = acc[mt][nt][3];
                    if (l == 0) {   // exact rank-1 t-term: tv * w0[576,:]
                        float w5760 = __ldg(w0_raw + 576 * 256 + col);
                        float w5761 = __ldg(w0_raw + 576 * 256 + col + 1);
                        a0 = fmaf(tv0, w5760, a0); a1 = fmaf(tv0, w5761, a1);
                        a2 = fmaf(tv1, w5760, a2); a3 = fmaf(tv1, w5761, a3);
                    }
                    float v00 = __sinf(W0F * (a0 + bb.x));
                    float v01 = __sinf(W0F * (a1 + bb.y));
                    float v10 = __sinf(W0F * (a2 + bb.x));
                    float v11 = __sinf(W0F * (a3 + bb.y));
                    __half h00 = __float2half_rn(v00), h01 = __float2half_rn(v01);
                    __half h10 = __float2half_rn(v10), h11 = __float2half_rn(v11);
                    __half l00 = __float2half_rn(v00 - __half2float(h00));
                    __half l01 = __float2half_rn(v01 - __half2float(h01));
                    __half l10 = __float2half_rn(v10 - __half2float(h10));
                    __half l11 = __float2half_rn(v11 - __half2float(h11));
                    uint32_t o0 = (uint32_t)((r0 * SA + col) * 2);
                    uint32_t o1 = (uint32_t)((r1 * SA + col) * 2);
                    *(__half2*)(smem + SM_AHI + o0) = __halves2half2(h00, h01);
                    *(__half2*)(smem + SM_ALO + o0) = __halves2half2(l00, l01);
                    *(__half2*)(smem + SM_AHI + o1) = __halves2half2(h10, h11);
                    *(__half2*)(smem + SM_ALO + o1) = __halves2half2(l10, l11);
                }
            }
        }
    }

    // ---------------- L4: 256 -> 27 in fp32 FFMA ----------------
    {
        float* ws = (float*)(smem + SM_BHI);          // 256*27 floats = 27648B
        for (int i = tid; i < 256 * 27; i += 512) ws[i] = __ldg(w4 + i);
        __syncthreads();

        const int q  = tid >> 2;                      // 0..127
        const int cj = tid & 3;
        const __half* Ahp = (const __half*)(smem + SM_AHI) + q * SA;
        const __half* Alp = (const __half*)(smem + SM_ALO) + q * SA;
        float a4[7];
        #pragma unroll
        for (int j = 0; j < 7; j++) a4[j] = 0.0f;
        #pragma unroll 4
        for (int k = 0; k < 256; k++) {
            float a = __half2float(Ahp[k]) + __half2float(Alp[k]);
            #pragma unroll
            for (int j = 0; j < 7; j++) {
                int c = cj + 4 * j;
                if (c < 27) a4[j] = fmaf(a, ws[k * 27 + c], a4[j]);
            }
        }
        const int qg = qbase + q;
        #pragma unroll
        for (int j = 0; j < 7; j++) {
            int c = cj + 4 * j;
            if (c < 27) g_pat[qg * 27 + c] = a4[j] + __ldg(b4 + c);
        }
    }
}

// ---------------- fold3 ----------------
__global__ void fold_kernel(float* __restrict__ out) {
    int idx = blockIdx.x * blockDim.x + threadIdx.x;
    if (idx >= 2 * QN) return;
    int b = idx >> 16;
    int p = idx & (QN - 1);
    int y = p >> 8, x = p & 255;
    float s0 = 0.f, s1 = 0.f, s2 = 0.f;
    #pragma unroll
    for (int i = 0; i < 3; i++) {
        int yy = y + 1 - i;
        if (yy < 0 || yy >= HH) continue;
        #pragma unroll
        for (int j = 0; j < 3; j++) {
            int xx = x + 1 - j;
            if (xx < 0 || xx >= WWI) continue;
            const float* pp = g_pat + (b * QN + yy * WWI + xx) * 27 + i * 3 + j;
            s0 += pp[0];
            s1 += pp[9];
            s2 += pp[18];
        }
    }
    out[(b * 3 + 0) * QN + p] = s0;
    out[(b * 3 + 1) * QN + p] = s1;
    out[(b * 3 + 2) * QN + p] = s2;
}

extern "C" void kernel_launch(void* const* d_in, const int* in_sizes, int n_in,
                              void* d_out, int out_size) {
    const float* feat  = (const float*)d_in[0];
    const float* coord = (const float*)d_in[1];
    const float* w0 = (const float*)d_in[2];
    const float* b0 = (const float*)d_in[3];
    const float* w1 = (const float*)d_in[4];
    const float* b1 = (const float*)d_in[5];
    const float* w2 = (const float*)d_in[6];
    const float* b2 = (const float*)d_in[7];
    const float* w3 = (const float*)d_in[8];
    const float* b3 = (const float*)d_in[9];
    const float* w4 = (const float*)d_in[10];
    const float* b4 = (const float*)d_in[11];
    float* out = (float*)d_out;

    prep_kernel<<<(WT_ELEMS + 255) / 256, 256>>>(w0, w1, w2, w3);

    cudaFuncSetAttribute(mlp_hmma, cudaFuncAttributeMaxDynamicSharedMemorySize, SM_TOTAL);
    mlp_hmma<<<(2 * QN) / MQ, 512, SM_TOTAL>>>(feat, coord, w0, b0, b1, b2, b3, w4, b4);

    fold_kernel<<<(2 * QN + 255) / 256, 256>>>(out);
}